// round 4
// baseline (speedup 1.0000x reference)
#include <cuda_runtime.h>

#define NN   6144          // nodes
#define INF_ 256           // in features
#define H    4             // heads
#define D    64            // hidden per head
#define HD   256           // H*D
#define LOG2E 1.4426950408889634f

#define JSPLIT 8
#define BI 64
#define BJ 32
#define NJ (NN / JSPLIT)       // 768 columns per split
#define NCH (NJ / BJ)          // 24 chunks

typedef unsigned long long u64;

// ---------------- packed f32x2 helpers (sm_103a FFMA2 path) ----------------
__device__ __forceinline__ void fma2(u64& d, u64 a, u64 b) {
    asm("fma.rn.f32x2 %0, %1, %2, %0;" : "+l"(d) : "l"(a), "l"(b));
}
__device__ __forceinline__ void add2(u64& d, u64 a) {
    asm("add.rn.f32x2 %0, %0, %1;" : "+l"(d) : "l"(a));
}
__device__ __forceinline__ void unpack2(u64 v, float& lo, float& hi) {
    asm("mov.b64 {%0, %1}, %2;" : "=f"(lo), "=f"(hi) : "l"(v));
}

// ---------------- scratch (device globals; no allocation allowed) ----------
__device__ float g_ht [NN * HD];                  // 6.29 MB : ht[n][h*64+d]
__device__ float g_src[H * NN];                   // pre-scaled by log2e
__device__ float g_tgt[H * NN];
__device__ float g_O  [(size_t)JSPLIT * H * NN * D];   // 50.3 MB partial numerators
__device__ float g_den[JSPLIT * H * NN];               // partial denominators

// ---------------- kernel 1: ht = h @ W  (6144x256 @ 256x256) ---------------
__global__ void __launch_bounds__(256) gemm_htW(const float* __restrict__ A,
                                                const float* __restrict__ B) {
    __shared__ float sA[16 * 68];   // [k][m] transposed, padded
    __shared__ float sB[16 * 64];   // [k][n]
    int t  = threadIdx.x;
    int n0 = blockIdx.x * 64;
    int m0 = blockIdx.y * 64;
    int tx = t & 15, ty = t >> 4;

    float acc[4][4] = {};
    int mA = t >> 2, kA = (t & 3) * 4;   // A loader coords
    int kB = t >> 4, nB = (t & 15) * 4;  // B loader coords

    for (int k0 = 0; k0 < INF_; k0 += 16) {
        float4 av = *(const float4*)&A[(m0 + mA) * INF_ + k0 + kA];
        float4 bv = *(const float4*)&B[(k0 + kB) * HD + n0 + nB];
        sA[(kA + 0) * 68 + mA] = av.x;
        sA[(kA + 1) * 68 + mA] = av.y;
        sA[(kA + 2) * 68 + mA] = av.z;
        sA[(kA + 3) * 68 + mA] = av.w;
        *(float4*)&sB[kB * 64 + nB] = bv;
        __syncthreads();
#pragma unroll
        for (int k = 0; k < 16; k++) {
            float4 a4 = *(float4*)&sA[k * 68 + ty * 4];
            float4 b4 = *(float4*)&sB[k * 64 + tx * 4];
            float ar[4] = {a4.x, a4.y, a4.z, a4.w};
            float br[4] = {b4.x, b4.y, b4.z, b4.w};
#pragma unroll
            for (int i = 0; i < 4; i++)
#pragma unroll
                for (int j = 0; j < 4; j++)
                    acc[i][j] += ar[i] * br[j];
        }
        __syncthreads();
    }
#pragma unroll
    for (int i = 0; i < 4; i++) {
        float4 o = make_float4(acc[i][0], acc[i][1], acc[i][2], acc[i][3]);
        *(float4*)&g_ht[(size_t)(m0 + ty * 4 + i) * HD + n0 + tx * 4] = o;
    }
}

// ---------------- kernel 2: src/tgt projections ----------------------------
__global__ void __launch_bounds__(256) src_tgt_k(const float* __restrict__ a) {
    int gw   = (blockIdx.x * blockDim.x + threadIdx.x) >> 5;
    int lane = threadIdx.x & 31;
    if (gw >= NN * H) return;
    int n = gw >> 2, h = gw & 3;
    float2 v  = *(const float2*)&g_ht[(size_t)n * HD + h * D + 2 * lane];
    const float* ap = a + h * 2 * D;                  // a[h][0:128]
    float2 as = *(const float2*)&ap[2 * lane];        // a_src
    float2 at = *(const float2*)&ap[D + 2 * lane];    // a_tgt
    float s = v.x * as.x + v.y * as.y;
    float tt = v.x * at.x + v.y * at.y;
#pragma unroll
    for (int off = 16; off > 0; off >>= 1) {
        s  += __shfl_xor_sync(0xffffffffu, s, off);
        tt += __shfl_xor_sync(0xffffffffu, tt, off);
    }
    if (lane == 0) {
        g_src[h * NN + n] = s  * LOG2E;
        g_tgt[h * NN + n] = tt * LOG2E;
    }
}

// ---------------- kernel 3: fused masked-exp + P@V, FFMA2 mainloop ---------
// block = 64 threads (2 warps), tile: 64 rows x 64 d, chunks of 32 columns.
// P@V uses packed fma.rn.f32x2: rows paired from sW (contiguous), V staged
// duplicated in sVd so {v,v} pairs load directly. IEEE fp32 per lane.
__global__ void __launch_bounds__(64) gat_attn(const int* __restrict__ adj) {
    __shared__ float sW  [BJ * 68];    // [k][r], stride 68
    __shared__ float sVd [BJ * 128];   // [k][2d] duplicated: {v,v} pairs
    __shared__ float sSrc[BI];

    int t  = threadIdx.x;
    int i0 = blockIdx.x * BI;
    int h  = blockIdx.y;
    int js = blockIdx.z;
    int j0base = js * NJ;

    if (t < BI) sSrc[t] = g_src[h * NN + i0 + t];
    __syncthreads();

    u64 acc2[4][8];                    // [row-pair][j] packed {r_even, r_odd}
#pragma unroll
    for (int i = 0; i < 4; i++)
#pragma unroll
        for (int j = 0; j < 8; j++) acc2[i][j] = 0ull;
    u64 dacc2[4] = {0ull, 0ull, 0ull, 0ull};

    int jlane = t & 31, rb = t >> 5;       // w-gen mapping
    int tr = t & 7, tc = t >> 3;           // gemm mapping: rows tr*8.., d tc*8..

    for (int c = 0; c < NCH; c++) {
        int j0 = j0base + c * BJ;
        // stage V tile (32 x 64 f32) duplicated into sVd
#pragma unroll
        for (int i = 0; i < 8; i++) {
            int q = t + 64 * i;
            int k = q >> 4, d4 = (q & 15) * 4;
            float4 v = *(const float4*)&g_ht[(size_t)(j0 + k) * HD + h * D + d4];
            *(float4*)&sVd[k * 128 + 2 * d4]     = make_float4(v.x, v.x, v.y, v.y);
            *(float4*)&sVd[k * 128 + 2 * d4 + 4] = make_float4(v.z, v.z, v.w, v.w);
        }
        // generate weights: w = adj ? 2^leaky(src'+tgt') : 0
        float tg = g_tgt[h * NN + j0 + jlane];
        const int* ap = adj + (size_t)(i0 + rb * 32) * NN + j0 + jlane;
#pragma unroll
        for (int half = 0; half < 2; half++) {
            int avb[16];
#pragma unroll
            for (int m = 0; m < 16; m++)
                avb[m] = __ldg(&ap[(size_t)(half * 16 + m) * NN]);
#pragma unroll
            for (int m = 0; m < 16; m++) {
                int r  = rb * 32 + half * 16 + m;
                float e  = sSrc[r] + tg;
                float lk = fmaxf(e, 0.2f * e);
                float w;
                asm("ex2.approx.ftz.f32 %0, %1;" : "=f"(w) : "f"(lk));
                w = avb[m] ? w : 0.0f;
                sW[jlane * 68 + r] = w;
            }
        }
        __syncthreads();
        // O += P @ V : 32 FFMA2 per k per thread (= 64 MACs)
#pragma unroll
        for (int k = 0; k < BJ; k++) {
            ulonglong2 pA = *(ulonglong2*)&sW[k * 68 + tr * 8];
            ulonglong2 pB = *(ulonglong2*)&sW[k * 68 + tr * 8 + 4];
            ulonglong2 vA = *(ulonglong2*)&sVd[k * 128 + tc * 16];
            ulonglong2 vB = *(ulonglong2*)&sVd[k * 128 + tc * 16 + 4];
            ulonglong2 vC = *(ulonglong2*)&sVd[k * 128 + tc * 16 + 8];
            ulonglong2 vD = *(ulonglong2*)&sVd[k * 128 + tc * 16 + 12];
            u64 pw[4] = {pA.x, pA.y, pB.x, pB.y};
            u64 vv[8] = {vA.x, vA.y, vB.x, vB.y, vC.x, vC.y, vD.x, vD.y};
#pragma unroll
            for (int i = 0; i < 4; i++)
#pragma unroll
                for (int j = 0; j < 8; j++)
                    fma2(acc2[i][j], pw[i], vv[j]);
            if (tc == 0) {
#pragma unroll
                for (int i = 0; i < 4; i++) add2(dacc2[i], pw[i]);
            }
        }
        __syncthreads();
    }

    float* Op = &g_O[((size_t)(js * H + h) * NN) * D];
#pragma unroll
    for (int i = 0; i < 4; i++) {
        float r0[8], r1[8];
#pragma unroll
        for (int j = 0; j < 8; j++) unpack2(acc2[i][j], r0[j], r1[j]);
        int ra = i0 + tr * 8 + 2 * i;
        *(float4*)&Op[(size_t)ra * D + tc * 8]     = make_float4(r0[0], r0[1], r0[2], r0[3]);
        *(float4*)&Op[(size_t)ra * D + tc * 8 + 4] = make_float4(r0[4], r0[5], r0[6], r0[7]);
        *(float4*)&Op[(size_t)(ra + 1) * D + tc * 8]     = make_float4(r1[0], r1[1], r1[2], r1[3]);
        *(float4*)&Op[(size_t)(ra + 1) * D + tc * 8 + 4] = make_float4(r1[4], r1[5], r1[6], r1[7]);
    }
    if (tc == 0) {
#pragma unroll
        for (int i = 0; i < 4; i++) {
            float d0, d1;
            unpack2(dacc2[i], d0, d1);
            int r = i0 + tr * 8 + 2 * i;
            g_den[(js * H + h) * NN + r]     = d0;
            g_den[(js * H + h) * NN + r + 1] = d1;
        }
    }
}

// ---------------- kernel 4: merge splits, normalize, mean over heads -------
__global__ void __launch_bounds__(256) reduce_out(float* __restrict__ out) {
    int idx = blockIdx.x * blockDim.x + threadIdx.x;
    if (idx >= NN * D) return;
    int i = idx >> 6, d = idx & 63;
    float s = 0.0f;
#pragma unroll
    for (int h = 0; h < H; h++) {
        float o = 0.0f, den = 0.0f;
#pragma unroll
        for (int js = 0; js < JSPLIT; js++) {
            o   += g_O[((size_t)(js * H + h) * NN + i) * D + d];
            den += g_den[(js * H + h) * NN + i];
        }
        if (den == 0.0f) den = 1.0f;   // unreachable with this graph density
        s += __fdividef(o, den);
    }
    out[idx] = 0.25f * s;
}

// ---------------- launch ---------------------------------------------------
extern "C" void kernel_launch(void* const* d_in, const int* in_sizes, int n_in,
                              void* d_out, int out_size) {
    const float* h   = (const float*)d_in[0];
    const int*   adj = (const int*)  d_in[1];
    const float* W   = (const float*)d_in[2];
    const float* a   = (const float*)d_in[3];
    float* out = (float*)d_out;

    gemm_htW<<<dim3(HD / 64, NN / 64), 256>>>(h, W);
    src_tgt_k<<<(NN * H * 32 + 255) / 256, 256>>>(a);
    gat_attn<<<dim3(NN / BI, H, JSPLIT), 64>>>(adj);
    reduce_out<<<(NN * D + 255) / 256, 256>>>(out);
}

// round 10
// speedup vs baseline: 1.4249x; 1.4249x over previous
#include <cuda_runtime.h>
#include <cuda_bf16.h>
#include <cstdint>

#define NN   6144
#define INF_ 256
#define H    4
#define D    64
#define HD   256
#define LOG2E 1.4426950408889634f

#define JSPLIT 2
#define MT   64                // rows per block
#define BKC  64                // K chunk (j's per chunk)
#define NJC  (NN / JSPLIT)     // 3072
#define NCHUNK (NJC / BKC)     // 48

#define PSTR 144               // padded row stride in bytes (72 bf16) — conflict-free ldmatrix

// static smem offsets (all 16B aligned)
#define SM_SRC  0              // 64 f32
#define SM_TGT  256            // 64 f32
#define SM_P_HI 512            // 64 x 72 bf16 = 9216 B
#define SM_P_LO (512 + 9216)
#define SM_V_HI (512 + 18432)  // VT[n][k] 64 x 72 bf16
#define SM_V_LO (512 + 27648)
#define SM_TOT  (512 + 36864)  // 37376 B

__device__ float g_ht [NN * HD];
__device__ float g_src[H * NN];
__device__ float g_tgt[H * NN];
__device__ float g_O  [(size_t)JSPLIT * H * NN * D];
__device__ float g_den[JSPLIT * H * NN];

// ---------------- helpers ---------------------------------------------------
__device__ __forceinline__ uint32_t smem_u32(const void* p) {
    uint32_t a;
    asm("{ .reg .u64 t; cvta.to.shared.u64 t, %1; cvt.u32.u64 %0, t; }"
        : "=r"(a) : "l"(p));
    return a;
}
__device__ __forceinline__ void ldsm_x4(uint32_t& r0, uint32_t& r1,
                                        uint32_t& r2, uint32_t& r3, uint32_t addr) {
    asm volatile("ldmatrix.sync.aligned.m8n8.x4.shared.b16 {%0,%1,%2,%3}, [%4];"
                 : "=r"(r0), "=r"(r1), "=r"(r2), "=r"(r3) : "r"(addr));
}
__device__ __forceinline__ void mma16816(float* c, uint32_t a0, uint32_t a1,
                                         uint32_t a2, uint32_t a3,
                                         uint32_t b0, uint32_t b1) {
    asm volatile(
        "mma.sync.aligned.m16n8k16.row.col.f32.bf16.bf16.f32 "
        "{%0,%1,%2,%3}, {%4,%5,%6,%7}, {%8,%9}, {%0,%1,%2,%3};"
        : "+f"(c[0]), "+f"(c[1]), "+f"(c[2]), "+f"(c[3])
        : "r"(a0), "r"(a1), "r"(a2), "r"(a3), "r"(b0), "r"(b1));
}
__device__ __forceinline__ uint32_t pack_bf16(__nv_bfloat16 lo, __nv_bfloat16 hi) {
    return (uint32_t)__bfloat16_as_ushort(hi) << 16 | __bfloat16_as_ushort(lo);
}

// ---------------- kernel 1: ht = h @ W  ------------------------------------
__global__ void __launch_bounds__(256) gemm_htW(const float* __restrict__ A,
                                                const float* __restrict__ B) {
    __shared__ float sA[16 * 68];
    __shared__ float sB[16 * 64];
    int t  = threadIdx.x;
    int n0 = blockIdx.x * 64;
    int m0 = blockIdx.y * 64;
    int tx = t & 15, ty = t >> 4;
    float acc[4][4] = {};
    int mA = t >> 2, kA = (t & 3) * 4;
    int kB = t >> 4, nB = (t & 15) * 4;
    for (int k0 = 0; k0 < INF_; k0 += 16) {
        float4 av = *(const float4*)&A[(m0 + mA) * INF_ + k0 + kA];
        float4 bv = *(const float4*)&B[(k0 + kB) * HD + n0 + nB];
        sA[(kA + 0) * 68 + mA] = av.x;
        sA[(kA + 1) * 68 + mA] = av.y;
        sA[(kA + 2) * 68 + mA] = av.z;
        sA[(kA + 3) * 68 + mA] = av.w;
        *(float4*)&sB[kB * 64 + nB] = bv;
        __syncthreads();
#pragma unroll
        for (int k = 0; k < 16; k++) {
            float4 a4 = *(float4*)&sA[k * 68 + ty * 4];
            float4 b4 = *(float4*)&sB[k * 64 + tx * 4];
            float ar[4] = {a4.x, a4.y, a4.z, a4.w};
            float br[4] = {b4.x, b4.y, b4.z, b4.w};
#pragma unroll
            for (int i = 0; i < 4; i++)
#pragma unroll
                for (int j = 0; j < 4; j++)
                    acc[i][j] += ar[i] * br[j];
        }
        __syncthreads();
    }
#pragma unroll
    for (int i = 0; i < 4; i++)
        *(float4*)&g_ht[(size_t)(m0 + ty * 4 + i) * HD + n0 + tx * 4] =
            make_float4(acc[i][0], acc[i][1], acc[i][2], acc[i][3]);
}

// ---------------- kernel 2: src/tgt ----------------------------------------
__global__ void __launch_bounds__(256) src_tgt_k(const float* __restrict__ a) {
    int gw   = (blockIdx.x * blockDim.x + threadIdx.x) >> 5;
    int lane = threadIdx.x & 31;
    if (gw >= NN * H) return;
    int n = gw >> 2, h = gw & 3;
    float2 v  = *(const float2*)&g_ht[(size_t)n * HD + h * D + 2 * lane];
    const float* ap = a + h * 2 * D;
    float2 as = *(const float2*)&ap[2 * lane];
    float2 at = *(const float2*)&ap[D + 2 * lane];
    float s = v.x * as.x + v.y * as.y;
    float tt = v.x * at.x + v.y * at.y;
#pragma unroll
    for (int off = 16; off > 0; off >>= 1) {
        s  += __shfl_xor_sync(0xffffffffu, s, off);
        tt += __shfl_xor_sync(0xffffffffu, tt, off);
    }
    if (lane == 0) {
        g_src[h * NN + n] = s  * LOG2E;
        g_tgt[h * NN + n] = tt * LOG2E;
    }
}

// ---------------- kernel 3: HMMA fused masked-softmax P@V -------------------
// 128 thr / 4 warps; tile 64 rows x 64 d; K chunks of 64; 3-term bf16 split
// via mma.sync.m16n8k16 (plain sm_103-compatible). Accumulators live in
// registers across all 48 chunks.
__global__ void __launch_bounds__(128) gat_attn_mma(const int* __restrict__ adj) {
    __shared__ __align__(16) char smem[SM_TOT];
    uint32_t sb = smem_u32(smem);
    float* sSrc = (float*)(smem + SM_SRC);
    float* sTgt = (float*)(smem + SM_TGT);

    int t = threadIdx.x, lane = t & 31, w = t >> 5;
    int i0 = blockIdx.x * MT;
    int h  = blockIdx.y;
    int js = blockIdx.z;
    int j0base = js * NJC;
    int hNN = h * NN;

    if (t < MT) sSrc[t] = g_src[hNN + i0 + t];

    // weight-gen mapping: row r, j-half jh
    int r  = t >> 1;
    int jh = (t & 1) * 32;
    // V-stage mapping: n row of VT, k-half
    int vn = t >> 1;
    int vkh = (t & 1) * 32;

    // ldmatrix lane addresses
    uint32_t aRow = (uint32_t)(16 * w + (lane & 15));
    uint32_t aCol = (uint32_t)((lane >> 4) * 16);            // bytes: 8 bf16
    uint32_t aOffH = sb + SM_P_HI + aRow * PSTR + aCol;
    uint32_t aOffL = sb + SM_P_LO + aRow * PSTR + aCol;
    uint32_t bRow = (uint32_t)(((lane >> 4) << 3) + (lane & 7));
    uint32_t bCol = (uint32_t)(((lane >> 3) & 1) * 16);      // bytes
    uint32_t bOffH = sb + SM_V_HI + bRow * PSTR + bCol;
    uint32_t bOffL = sb + SM_V_LO + bRow * PSTR + bCol;

    float acc[8][4];
#pragma unroll
    for (int nb = 0; nb < 8; nb++)
#pragma unroll
        for (int q = 0; q < 4; q++) acc[nb][q] = 0.0f;
    float dacc = 0.0f;

    __syncthreads();
    float mysrc = sSrc[r];

    for (int c = 0; c < NCHUNK; c++) {
        int j0 = j0base + c * BKC;
        __syncthreads();   // previous compute finished reading smem
        if (t < BKC) sTgt[t] = g_tgt[hNN + j0 + t];
        __syncthreads();

        // ---- P generation + bf16 split (row r, 32 j's)
        {
            const int4* ap = (const int4*)(adj + (size_t)(i0 + r) * NN + j0 + jh);
#pragma unroll
            for (int g = 0; g < 8; g++) {
                int4 av = __ldg(ap + g);
                int jj = jh + g * 4;
                float wv[4];
                int msk[4] = {av.x, av.y, av.z, av.w};
#pragma unroll
                for (int q = 0; q < 4; q++) {
                    float e  = mysrc + sTgt[jj + q];
                    float lk = fmaxf(e, 0.2f * e);
                    float ww;
                    asm("ex2.approx.ftz.f32 %0, %1;" : "=f"(ww) : "f"(lk));
                    wv[q] = msk[q] ? ww : 0.0f;
                }
                dacc += (wv[0] + wv[1]) + (wv[2] + wv[3]);
                __nv_bfloat16 hb[4], lb[4];
#pragma unroll
                for (int q = 0; q < 4; q++) {
                    hb[q] = __float2bfloat16_rn(wv[q]);
                    lb[q] = __float2bfloat16_rn(wv[q] - __bfloat162float(hb[q]));
                }
                uint32_t byte = (uint32_t)r * PSTR + (uint32_t)jj * 2;
                *(uint2*)(smem + SM_P_HI + byte) =
                    make_uint2(pack_bf16(hb[0], hb[1]), pack_bf16(hb[2], hb[3]));
                *(uint2*)(smem + SM_P_LO + byte) =
                    make_uint2(pack_bf16(lb[0], lb[1]), pack_bf16(lb[2], lb[3]));
            }
        }
        // ---- V staging transposed: VT[n][k] bf16 hi/lo (n=vn, 32 k's)
        {
            const float* vp = g_ht + (size_t)(j0 + vkh) * HD + h * D + vn;
            uint32_t vbyte = (uint32_t)vn * PSTR + (uint32_t)vkh * 2;
#pragma unroll
            for (int kk = 0; kk < 32; kk += 2) {
                float v0 = __ldg(vp + (size_t)kk * HD);
                float v1 = __ldg(vp + (size_t)(kk + 1) * HD);
                __nv_bfloat16 h0 = __float2bfloat16_rn(v0);
                __nv_bfloat16 h1 = __float2bfloat16_rn(v1);
                __nv_bfloat16 l0 = __float2bfloat16_rn(v0 - __bfloat162float(h0));
                __nv_bfloat16 l1 = __float2bfloat16_rn(v1 - __bfloat162float(h1));
                *(uint32_t*)(smem + SM_V_HI + vbyte + kk * 2) = pack_bf16(h0, h1);
                *(uint32_t*)(smem + SM_V_LO + vbyte + kk * 2) = pack_bf16(l0, l1);
            }
        }
        __syncthreads();

        // ---- compute: 4 k-steps x 4 n-tile-pairs, 3 mma each (hi*hi, hi*lo, lo*hi)
#pragma unroll
        for (int ks = 0; ks < 4; ks++) {
            uint32_t ah0, ah1, ah2, ah3, al0, al1, al2, al3;
            ldsm_x4(ah0, ah1, ah2, ah3, aOffH + ks * 32);
            ldsm_x4(al0, al1, al2, al3, aOffL + ks * 32);
#pragma unroll
            for (int p = 0; p < 4; p++) {
                uint32_t bh0, bh1, bh2, bh3, bl0, bl1, bl2, bl3;
                uint32_t bo = p * (16 * PSTR) + ks * 32;
                ldsm_x4(bh0, bh1, bh2, bh3, bOffH + bo);
                ldsm_x4(bl0, bl1, bl2, bl3, bOffL + bo);
                mma16816(acc[2 * p],     ah0, ah1, ah2, ah3, bh0, bh1);
                mma16816(acc[2 * p],     ah0, ah1, ah2, ah3, bl0, bl1);
                mma16816(acc[2 * p],     al0, al1, al2, al3, bh0, bh1);
                mma16816(acc[2 * p + 1], ah0, ah1, ah2, ah3, bh2, bh3);
                mma16816(acc[2 * p + 1], ah0, ah1, ah2, ah3, bl2, bl3);
                mma16816(acc[2 * p + 1], al0, al1, al2, al3, bh2, bh3);
            }
        }
    }

    // ---- denominator (fp32, exact): pair partials per row
    float dall = dacc + __shfl_xor_sync(0xffffffffu, dacc, 1);
    if ((t & 1) == 0)
        g_den[(js * H + h) * NN + i0 + r] = dall;

    // ---- epilogue: write accumulators to g_O
    {
        int g  = lane >> 2, tq = lane & 3;
        int r0 = i0 + 16 * w + g;
        float* Op = &g_O[((size_t)(js * H + h) * NN) * D];
#pragma unroll
        for (int nb = 0; nb < 8; nb++) {
            int col = 8 * nb + 2 * tq;
            *(float2*)&Op[(size_t)r0 * D + col]       = make_float2(acc[nb][0], acc[nb][1]);
            *(float2*)&Op[(size_t)(r0 + 8) * D + col] = make_float2(acc[nb][2], acc[nb][3]);
        }
    }
}

// ---------------- kernel 4: merge splits, normalize, mean over heads -------
__global__ void __launch_bounds__(256) reduce_out(float* __restrict__ out) {
    int idx = blockIdx.x * blockDim.x + threadIdx.x;
    if (idx >= NN * D) return;
    int i = idx >> 6, d = idx & 63;
    float s = 0.0f;
#pragma unroll
    for (int h = 0; h < H; h++) {
        float o = 0.0f, den = 0.0f;
#pragma unroll
        for (int js = 0; js < JSPLIT; js++) {
            o   += g_O[((size_t)(js * H + h) * NN + i) * D + d];
            den += g_den[(js * H + h) * NN + i];
        }
        if (den == 0.0f) den = 1.0f;
        s += __fdividef(o, den);
    }
    out[idx] = 0.25f * s;
}

// ---------------- launch ---------------------------------------------------
extern "C" void kernel_launch(void* const* d_in, const int* in_sizes, int n_in,
                              void* d_out, int out_size) {
    const float* h   = (const float*)d_in[0];
    const int*   adj = (const int*)  d_in[1];
    const float* W   = (const float*)d_in[2];
    const float* a   = (const float*)d_in[3];
    float* out = (float*)d_out;

    gemm_htW<<<dim3(HD / 64, NN / 64), 256>>>(h, W);
    src_tgt_k<<<(NN * H * 32 + 255) / 256, 256>>>(a);
    gat_attn_mma<<<dim3(NN / MT, H, JSPLIT), 128>>>(adj);
    reduce_out<<<(NN * D + 255) / 256, 256>>>(out);
}